// round 4
// baseline (speedup 1.0000x reference)
#include <cuda_runtime.h>
#include <math.h>

// Batched FFT: B=8192 rows, N=4096, complex fp32 (separate re/im), out = [Yre; Yim].
//
// Radix-16^3 four-step (same verified structure/layout as the 90.8us kernel):
//   n = n1*256 + n2, k = k2*16 + k1, n2 = p1*16 + p2, k2 = q2*16 + q1.
// Pass 1 (t=n2):   A[k1] = DFT16_{n1}(x[n1*256+t]) * W4096^{t*k1}   (table tw1)
// Exch 1 (pad 257)
// Pass 2 (k1,p2):  C[q1] = DFT16_{p1}(...) * W256^{p2*q1}           (table tw2)
// Exch 2
// Pass 3 (k1,q1):  Y[q2*256 + q1*16 + k1] = DFT16_{p2}(...)
//
// Changes vs round 1: twiddle sincosf+serial-recurrence replaced by precomputed
// global tables (L1-resident, lane-consecutive), and 5 CTAs/SM via launch bounds.

#define NFFT 4096
#define TPB  256

__device__ float2 g_tw1[16 * 256];  // tw1[k*256 + t] = W4096^{t*k}
__device__ float2 g_tw2[16 * 16];   // tw2[q*16 + p]  = W256^{p*q}

__global__ void init_twiddles() {
    int idx = blockIdx.x * blockDim.x + threadIdx.x;
    if (idx < 16 * 256) {
        int k = idx >> 8, t = idx & 255;
        double a = -(double)(t * k) / 2048.0;   // angle/pi = -2*t*k/4096
        double s, c;
        sincospi(a, &s, &c);
        g_tw1[idx] = make_float2((float)c, (float)s);
    } else if (idx < 16 * 256 + 16 * 16) {
        int j = idx - 16 * 256;
        int q = j >> 4, p = j & 15;
        double a = -(double)(p * q) / 128.0;    // angle/pi = -2*p*q/256
        double s, c;
        sincospi(a, &s, &c);
        g_tw2[j] = make_float2((float)c, (float)s);
    }
}

__device__ __forceinline__ float2 cmul(float2 a, float2 b) {
    return make_float2(fmaf(a.x, b.x, -a.y * b.y),
                       fmaf(a.x, b.y,  a.y * b.x));
}

__device__ __forceinline__ void dft4(float2 a, float2 b, float2 c, float2 d,
                                     float2& o0, float2& o1, float2& o2, float2& o3) {
    // forward DFT4 (W4 = -i)
    float2 s0 = make_float2(a.x + c.x, a.y + c.y);
    float2 s1 = make_float2(a.x - c.x, a.y - c.y);
    float2 s2 = make_float2(b.x + d.x, b.y + d.y);
    float2 s3 = make_float2(b.x - d.x, b.y - d.y);
    o0 = make_float2(s0.x + s2.x, s0.y + s2.y);
    o2 = make_float2(s0.x - s2.x, s0.y - s2.y);
    o1 = make_float2(s1.x + s3.y, s1.y - s3.x);   // s1 - i*s3
    o3 = make_float2(s1.x - s3.y, s1.y + s3.x);   // s1 + i*s3
}

// 16-point forward DFT, natural in -> natural out (radix-4 x radix-4).
__device__ __forceinline__ void fft16(float2 v[16]) {
    const float C1 = 0.92387953251128675613f;
    const float S1 = 0.38268343236508977173f;
    const float R  = 0.70710678118654752440f;

    float2 a[4][4];
#pragma unroll
    for (int l = 0; l < 4; l++)
        dft4(v[l], v[l + 4], v[l + 8], v[l + 12],
             a[l][0], a[l][1], a[l][2], a[l][3]);

    a[1][1] = cmul(a[1][1], make_float2( C1, -S1));
    a[1][2] = cmul(a[1][2], make_float2(  R,  -R));
    a[1][3] = cmul(a[1][3], make_float2( S1, -C1));
    a[2][1] = cmul(a[2][1], make_float2(  R,  -R));
    { float2 x = a[2][2]; a[2][2] = make_float2(x.y, -x.x); }
    a[2][3] = cmul(a[2][3], make_float2( -R,  -R));
    a[3][1] = cmul(a[3][1], make_float2( S1, -C1));
    a[3][2] = cmul(a[3][2], make_float2( -R,  -R));
    a[3][3] = cmul(a[3][3], make_float2(-C1,  S1));

#pragma unroll
    for (int p = 0; p < 4; p++)
        dft4(a[0][p], a[1][p], a[2][p], a[3][p],
             v[p], v[4 + p], v[8 + p], v[12 + p]);
}

__global__ void __launch_bounds__(TPB, 5)
fft4096_kernel(const float* __restrict__ xre,
               const float* __restrict__ xim,
               float* __restrict__ out,
               int batch) {
    __shared__ float2 sh[16 * 257];  // 32896 B (257-stride pad for exch 1)

    const int b = blockIdx.x;
    const int t = threadIdx.x;

    const float* xr = xre + (size_t)b * NFFT;
    const float* xi = xim + (size_t)b * NFFT;
    const float2* __restrict__ tw1 = g_tw1;
    const float2* __restrict__ tw2 = g_tw2;

    float2 v[16];
#pragma unroll
    for (int n1 = 0; n1 < 16; n1++)
        v[n1] = make_float2(xr[n1 * 256 + t], xi[n1 * 256 + t]);

    // ---- pass 1: DFT16 over n1, thread t = n2 ----
    fft16(v);

    // twiddle W4096^{t*k1} from table (lane-consecutive: coalesced L1 hits)
#pragma unroll
    for (int k1 = 1; k1 < 16; k1++)
        v[k1] = cmul(v[k1], tw1[k1 * 256 + t]);

    // ---- exchange 1: S1[k1*257 + n2] ----
#pragma unroll
    for (int k1 = 0; k1 < 16; k1++)
        sh[k1 * 257 + t] = v[k1];
    __syncthreads();

    {
        const int k1 = t & 15;
        const int p2 = t >> 4;
#pragma unroll
        for (int p1 = 0; p1 < 16; p1++)
            v[p1] = sh[k1 * 257 + p1 * 16 + p2];

        // ---- pass 2: DFT16 over p1 -> q1 ----
        fft16(v);

        // twiddle W256^{p2*q1} from table (2 distinct addrs per warp-load)
#pragma unroll
        for (int q1 = 1; q1 < 16; q1++)
            v[q1] = cmul(v[q1], tw2[q1 * 16 + p2]);
    }
    __syncthreads();

    // ---- exchange 2: S2[q1*256 + t] ----
#pragma unroll
    for (int q1 = 0; q1 < 16; q1++)
        sh[q1 * 256 + t] = v[q1];
    __syncthreads();

    {
        const int k1 = t & 15;
        const int q1 = t >> 4;
#pragma unroll
        for (int p2 = 0; p2 < 16; p2++)
            v[p2] = sh[q1 * 256 + p2 * 16 + k1];
    }

    // ---- pass 3: DFT16 over p2 -> q2;  Y[q2*256 + t] ----
    fft16(v);

    float* outre = out + (size_t)b * NFFT;
    float* outim = out + (size_t)batch * NFFT + (size_t)b * NFFT;
#pragma unroll
    for (int q2 = 0; q2 < 16; q2++) {
        outre[q2 * 256 + t] = v[q2].x;
        outim[q2 * 256 + t] = v[q2].y;
    }
}

extern "C" void kernel_launch(void* const* d_in, const int* in_sizes, int n_in,
                              void* d_out, int out_size) {
    const float* xre = (const float*)d_in[0];
    const float* xim = (const float*)d_in[1];
    float* out = (float*)d_out;
    const int batch = in_sizes[0] / NFFT;

    init_twiddles<<<(16 * 256 + 16 * 16 + 255) / 256, 256>>>();
    fft4096_kernel<<<batch, TPB>>>(xre, xim, out, batch);
}

// round 5
// speedup vs baseline: 1.1535x; 1.1535x over previous
#include <cuda_runtime.h>
#include <math.h>

// Batched FFT: B=8192 rows, N=4096, complex fp32 (separate re/im), out = [Yre; Yim].
//
// Round-1 radix-16^3 four-step math (verified), now persistent-CTA with a
// cp.async input-staging pipeline that ALIASES the exchange smem buffer:
//   ... exch-2 reads -> sync -> cp.async(next row -> smem) -> pass 3 -> stores
//   loop top: cp.async.wait + sync -> read inputs from smem (LDS, no DRAM stall)
// Twiddle bases (sincosf) hoisted out of the loop; per-row powers via
// log-depth squaring. Streaming stores.

#define NFFT 4096
#define TPB  256

__device__ __forceinline__ float2 cmul(float2 a, float2 b) {
    return make_float2(fmaf(a.x, b.x, -a.y * b.y),
                       fmaf(a.x, b.y,  a.y * b.x));
}

__device__ __forceinline__ void dft4(float2 a, float2 b, float2 c, float2 d,
                                     float2& o0, float2& o1, float2& o2, float2& o3) {
    // forward DFT4 (W4 = -i)
    float2 s0 = make_float2(a.x + c.x, a.y + c.y);
    float2 s1 = make_float2(a.x - c.x, a.y - c.y);
    float2 s2 = make_float2(b.x + d.x, b.y + d.y);
    float2 s3 = make_float2(b.x - d.x, b.y - d.y);
    o0 = make_float2(s0.x + s2.x, s0.y + s2.y);
    o2 = make_float2(s0.x - s2.x, s0.y - s2.y);
    o1 = make_float2(s1.x + s3.y, s1.y - s3.x);   // s1 - i*s3
    o3 = make_float2(s1.x - s3.y, s1.y + s3.x);   // s1 + i*s3
}

// 16-point forward DFT, natural in -> natural out (radix-4 x radix-4).
__device__ __forceinline__ void fft16(float2 v[16]) {
    const float C1 = 0.92387953251128675613f;
    const float S1 = 0.38268343236508977173f;
    const float R  = 0.70710678118654752440f;

    float2 a[4][4];
#pragma unroll
    for (int l = 0; l < 4; l++)
        dft4(v[l], v[l + 4], v[l + 8], v[l + 12],
             a[l][0], a[l][1], a[l][2], a[l][3]);

    a[1][1] = cmul(a[1][1], make_float2( C1, -S1));
    a[1][2] = cmul(a[1][2], make_float2(  R,  -R));
    a[1][3] = cmul(a[1][3], make_float2( S1, -C1));
    a[2][1] = cmul(a[2][1], make_float2(  R,  -R));
    { float2 x = a[2][2]; a[2][2] = make_float2(x.y, -x.x); }
    a[2][3] = cmul(a[2][3], make_float2( -R,  -R));
    a[3][1] = cmul(a[3][1], make_float2( S1, -C1));
    a[3][2] = cmul(a[3][2], make_float2( -R,  -R));
    a[3][3] = cmul(a[3][3], make_float2(-C1,  S1));

#pragma unroll
    for (int p = 0; p < 4; p++)
        dft4(a[0][p], a[1][p], a[2][p], a[3][p],
             v[p], v[4 + p], v[8 + p], v[12 + p]);
}

// v[k] *= w^k, k=1..15, log-depth power generation (depth ~4 vs 15 serial).
__device__ __forceinline__ void twiddle16(float2 v[16], float2 w) {
    float2 p2 = cmul(w, w);
    float2 p4 = cmul(p2, p2);
    float2 p8 = cmul(p4, p4);
    float2 p3 = cmul(p2, w);
    float2 p5 = cmul(p4, w);
    float2 p6 = cmul(p4, p2);
    float2 p7 = cmul(p4, p3);
    v[1]  = cmul(v[1],  w);
    v[2]  = cmul(v[2],  p2);
    v[3]  = cmul(v[3],  p3);
    v[4]  = cmul(v[4],  p4);
    v[5]  = cmul(v[5],  p5);
    v[6]  = cmul(v[6],  p6);
    v[7]  = cmul(v[7],  p7);
    v[8]  = cmul(v[8],  p8);
    v[9]  = cmul(v[9],  cmul(p8, w));
    v[10] = cmul(v[10], cmul(p8, p2));
    v[11] = cmul(v[11], cmul(p8, p3));
    v[12] = cmul(v[12], cmul(p8, p4));
    v[13] = cmul(v[13], cmul(p8, p5));
    v[14] = cmul(v[14], cmul(p8, p6));
    v[15] = cmul(v[15], cmul(p8, p7));
}

__device__ __forceinline__ void cp_async16(unsigned dst_smem, const void* src) {
    asm volatile("cp.async.cg.shared.global [%0], [%1], 16;"
                 :: "r"(dst_smem), "l"(src) : "memory");
}

__global__ void __launch_bounds__(TPB, 4)
fft4096_pipe(const float* __restrict__ xre,
             const float* __restrict__ xim,
             float* __restrict__ out,
             int batch) {
    __shared__ float2 sh[16 * 257];          // exchange buffer (32896 B)
    float* S = (float*)sh;                   // staging alias: re [0,4096), im [4096,8192)

    const int t  = threadIdx.x;
    const int G  = gridDim.x;
    const int k1 = t & 15;
    const int hi = t >> 4;                   // p2 in pass 2, q1 in pass 3

    // hoisted twiddle bases (depend only on t)
    float s1w, c1w, s2w, c2w;
    sincosf(-6.2831853071795864769f * (float)t  / 4096.0f, &s1w, &c1w);
    sincosf(-6.2831853071795864769f * (float)hi /  256.0f, &s2w, &c2w);
    const float2 w1 = make_float2(c1w, s1w);
    const float2 w2 = make_float2(c2w, s2w);

    const unsigned sbase = (unsigned)__cvta_generic_to_shared(S);

    // prologue: stage first row
    {
        int r0 = blockIdx.x;
        if (r0 < batch) {
            const char* gre = (const char*)(xre + (size_t)r0 * NFFT);
            const char* gim = (const char*)(xim + (size_t)r0 * NFFT);
#pragma unroll
            for (int j = 0; j < 4; j++) {
                cp_async16(sbase + (unsigned)((j * 256 + t) * 16),         gre + (j * 256 + t) * 16);
                cp_async16(sbase + (unsigned)(16384 + (j * 256 + t) * 16), gim + (j * 256 + t) * 16);
            }
            asm volatile("cp.async.commit_group;" ::: "memory");
        }
    }

    for (int row = blockIdx.x; row < batch; row += G) {
        // staged input ready
        asm volatile("cp.async.wait_group 0;" ::: "memory");
        __syncthreads();

        float2 v[16];
#pragma unroll
        for (int n1 = 0; n1 < 16; n1++)
            v[n1] = make_float2(S[n1 * 256 + t], S[4096 + n1 * 256 + t]);

        // ---- pass 1: DFT16 over n1 (thread t = n2), twiddle W4096^{t*k1} ----
        fft16(v);
        twiddle16(v, w1);

        __syncthreads();   // all staged reads done -> exchange may overwrite

        // ---- exchange 1: sh[k1*257 + n2] ----
#pragma unroll
        for (int k = 0; k < 16; k++)
            sh[k * 257 + t] = v[k];
        __syncthreads();
#pragma unroll
        for (int p1 = 0; p1 < 16; p1++)
            v[p1] = sh[k1 * 257 + p1 * 16 + hi];

        // ---- pass 2: DFT16 over p1, twiddle W256^{p2*q1} ----
        fft16(v);
        twiddle16(v, w2);

        __syncthreads();   // exch-1 reads done

        // ---- exchange 2: sh[q1*256 + t] ----
#pragma unroll
        for (int q = 0; q < 16; q++)
            sh[q * 256 + t] = v[q];
        __syncthreads();
#pragma unroll
        for (int p2 = 0; p2 < 16; p2++)
            v[p2] = sh[hi * 256 + p2 * 16 + k1];

        __syncthreads();   // exch-2 reads done by ALL -> smem free for staging

        // prefetch next row into smem, overlapping pass-3 compute + stores
        {
            int nr = row + G;
            if (nr < batch) {
                const char* gre = (const char*)(xre + (size_t)nr * NFFT);
                const char* gim = (const char*)(xim + (size_t)nr * NFFT);
#pragma unroll
                for (int j = 0; j < 4; j++) {
                    cp_async16(sbase + (unsigned)((j * 256 + t) * 16),         gre + (j * 256 + t) * 16);
                    cp_async16(sbase + (unsigned)(16384 + (j * 256 + t) * 16), gim + (j * 256 + t) * 16);
                }
                asm volatile("cp.async.commit_group;" ::: "memory");
            }
        }

        // ---- pass 3: DFT16 over p2 -> q2;  Y[q2*256 + t] ----
        fft16(v);

        float* outre = out + (size_t)row * NFFT;
        float* outim = out + (size_t)batch * NFFT + (size_t)row * NFFT;
#pragma unroll
        for (int q2 = 0; q2 < 16; q2++) {
            __stcs(&outre[q2 * 256 + t], v[q2].x);
            __stcs(&outim[q2 * 256 + t], v[q2].y);
        }
    }
}

extern "C" void kernel_launch(void* const* d_in, const int* in_sizes, int n_in,
                              void* d_out, int out_size) {
    const float* xre = (const float*)d_in[0];
    const float* xim = (const float*)d_in[1];
    float* out = (float*)d_out;
    const int batch = in_sizes[0] / NFFT;

    int sms = 0;
    cudaDeviceGetAttribute(&sms, cudaDevAttrMultiProcessorCount, 0);
    if (sms <= 0) sms = 148;
    int grid = sms * 4;
    if (grid > batch) grid = batch;

    fft4096_pipe<<<grid, TPB>>>(xre, xim, out, batch);
}

// round 6
// speedup vs baseline: 1.3469x; 1.1677x over previous
#include <cuda_runtime.h>
#include <math.h>

// Batched FFT: B=8192 rows, N=4096, complex fp32 (separate re/im), out = [Yre; Yim].
//
// Round-1 radix-16^3 four-step kernel (best so far: 86.6us kernel, DRAM 70.7%),
// single change: __launch_bounds__(256,5) to force regs<=51 -> 5 CTAs/SM
// (40 warps) for more cross-CTA phase overlap. Streaming cache hints on the
// global load/store paths (pure streaming data).
//
//   n = n1*256 + n2, k = k2*16 + k1, n2 = p1*16 + p2, k2 = q2*16 + q1.
// Pass 1 (t=n2):   A[k1] = DFT16_{n1}(x[n1*256+t]) * W4096^{t*k1}
// Exch 1 (pad 257)
// Pass 2 (k1,p2):  C[q1] = DFT16_{p1}(...) * W256^{p2*q1}
// Exch 2
// Pass 3 (k1,q1):  Y[q2*256 + q1*16 + k1] = DFT16_{p2}(...)

#define NFFT 4096
#define TPB  256

__device__ __forceinline__ float2 cmul(float2 a, float2 b) {
    return make_float2(fmaf(a.x, b.x, -a.y * b.y),
                       fmaf(a.x, b.y,  a.y * b.x));
}

__device__ __forceinline__ void dft4(float2 a, float2 b, float2 c, float2 d,
                                     float2& o0, float2& o1, float2& o2, float2& o3) {
    // forward DFT4 (W4 = -i)
    float2 s0 = make_float2(a.x + c.x, a.y + c.y);
    float2 s1 = make_float2(a.x - c.x, a.y - c.y);
    float2 s2 = make_float2(b.x + d.x, b.y + d.y);
    float2 s3 = make_float2(b.x - d.x, b.y - d.y);
    o0 = make_float2(s0.x + s2.x, s0.y + s2.y);
    o2 = make_float2(s0.x - s2.x, s0.y - s2.y);
    o1 = make_float2(s1.x + s3.y, s1.y - s3.x);   // s1 - i*s3
    o3 = make_float2(s1.x - s3.y, s1.y + s3.x);   // s1 + i*s3
}

// 16-point forward DFT, natural in -> natural out (radix-4 x radix-4).
__device__ __forceinline__ void fft16(float2 v[16]) {
    const float C1 = 0.92387953251128675613f;
    const float S1 = 0.38268343236508977173f;
    const float R  = 0.70710678118654752440f;

    float2 a[4][4];
#pragma unroll
    for (int l = 0; l < 4; l++)
        dft4(v[l], v[l + 4], v[l + 8], v[l + 12],
             a[l][0], a[l][1], a[l][2], a[l][3]);

    a[1][1] = cmul(a[1][1], make_float2( C1, -S1));
    a[1][2] = cmul(a[1][2], make_float2(  R,  -R));
    a[1][3] = cmul(a[1][3], make_float2( S1, -C1));
    a[2][1] = cmul(a[2][1], make_float2(  R,  -R));
    { float2 x = a[2][2]; a[2][2] = make_float2(x.y, -x.x); }
    a[2][3] = cmul(a[2][3], make_float2( -R,  -R));
    a[3][1] = cmul(a[3][1], make_float2( S1, -C1));
    a[3][2] = cmul(a[3][2], make_float2( -R,  -R));
    a[3][3] = cmul(a[3][3], make_float2(-C1,  S1));

#pragma unroll
    for (int p = 0; p < 4; p++)
        dft4(a[0][p], a[1][p], a[2][p], a[3][p],
             v[p], v[4 + p], v[8 + p], v[12 + p]);
}

__global__ void __launch_bounds__(TPB, 5)
fft4096_kernel(const float* __restrict__ xre,
               const float* __restrict__ xim,
               float* __restrict__ out,
               int batch) {
    __shared__ float2 sh[16 * 257];  // 32896 B (257-stride pad for exch 1)

    const int b = blockIdx.x;
    const int t = threadIdx.x;

    const float* xr = xre + (size_t)b * NFFT;
    const float* xi = xim + (size_t)b * NFFT;

    float2 v[16];
#pragma unroll
    for (int n1 = 0; n1 < 16; n1++)
        v[n1] = make_float2(__ldcs(&xr[n1 * 256 + t]), __ldcs(&xi[n1 * 256 + t]));

    // ---- pass 1: DFT16 over n1, thread t = n2 ----
    fft16(v);

    // twiddle W4096^{t*k1} via recurrence from one sincos
    {
        float s, c;
        sincosf(-6.2831853071795864769f * (float)t / 4096.0f, &s, &c);
        float2 w  = make_float2(c, s);
        float2 wk = w;
#pragma unroll
        for (int k1 = 1; k1 < 16; k1++) {
            v[k1] = cmul(v[k1], wk);
            wk = cmul(wk, w);
        }
    }

    // ---- exchange 1: S1[k1*257 + n2] ----
#pragma unroll
    for (int k1 = 0; k1 < 16; k1++)
        sh[k1 * 257 + t] = v[k1];
    __syncthreads();

    {
        const int k1 = t & 15;
        const int p2 = t >> 4;
#pragma unroll
        for (int p1 = 0; p1 < 16; p1++)
            v[p1] = sh[k1 * 257 + p1 * 16 + p2];

        // ---- pass 2: DFT16 over p1 -> q1 ----
        fft16(v);

        // twiddle W256^{p2*q1}
        float s, c;
        sincosf(-6.2831853071795864769f * (float)p2 / 256.0f, &s, &c);
        float2 w  = make_float2(c, s);
        float2 wk = w;
#pragma unroll
        for (int q1 = 1; q1 < 16; q1++) {
            v[q1] = cmul(v[q1], wk);
            wk = cmul(wk, w);
        }
    }
    __syncthreads();

    // ---- exchange 2: S2[q1*256 + t] ----
#pragma unroll
    for (int q1 = 0; q1 < 16; q1++)
        sh[q1 * 256 + t] = v[q1];
    __syncthreads();

    {
        const int k1 = t & 15;
        const int q1 = t >> 4;
#pragma unroll
        for (int p2 = 0; p2 < 16; p2++)
            v[p2] = sh[q1 * 256 + p2 * 16 + k1];
    }

    // ---- pass 3: DFT16 over p2 -> q2;  Y[q2*256 + t] ----
    fft16(v);

    float* outre = out + (size_t)b * NFFT;
    float* outim = out + (size_t)batch * NFFT + (size_t)b * NFFT;
#pragma unroll
    for (int q2 = 0; q2 < 16; q2++) {
        __stcs(&outre[q2 * 256 + t], v[q2].x);
        __stcs(&outim[q2 * 256 + t], v[q2].y);
    }
}

extern "C" void kernel_launch(void* const* d_in, const int* in_sizes, int n_in,
                              void* d_out, int out_size) {
    const float* xre = (const float*)d_in[0];
    const float* xim = (const float*)d_in[1];
    float* out = (float*)d_out;
    const int batch = in_sizes[0] / NFFT;

    fft4096_kernel<<<batch, TPB>>>(xre, xim, out, batch);
}

// round 7
// speedup vs baseline: 1.4112x; 1.0477x over previous
#include <cuda_runtime.h>
#include <math.h>

// Batched FFT: B=8192 rows, N=4096, complex fp32 (separate re/im), out = [Yre; Yim].
//
// Round-1 radix-16^3 four-step structure (best: 86.6us kernel), with all complex
// arithmetic converted to sm_103a packed f32x2 (FFMA2/FADD2 via inline PTX;
// ptxas never auto-generates these). Complex values stay packed (re,im) in
// 64-bit register pairs end-to-end; smem exchanges store the packed word.
//
//   n = n1*256 + n2, k = k2*16 + k1, n2 = p1*16 + p2, k2 = q2*16 + q1.
// Pass 1 (t=n2):   A[k1] = DFT16_{n1}(x[n1*256+t]) * W4096^{t*k1}
// Exch 1 (pad 257)
// Pass 2 (k1,p2):  C[q1] = DFT16_{p1}(...) * W256^{p2*q1}
// Exch 2
// Pass 3 (k1,q1):  Y[q2*256 + t] = DFT16_{p2}(...)

#define NFFT 4096
#define TPB  256

typedef unsigned long long c64;   // packed complex: lo 32 = re, hi 32 = im

__device__ __forceinline__ c64 cpack(float re, float im) {
    c64 r;
    asm("mov.b64 %0, {%1, %2};" : "=l"(r) : "f"(re), "f"(im));
    return r;
}
__device__ __forceinline__ void cunpack(c64 v, float& re, float& im) {
    asm("mov.b64 {%0, %1}, %2;" : "=f"(re), "=f"(im) : "l"(v));
}
__device__ __forceinline__ c64 padd(c64 a, c64 b) {
    c64 r;
    asm("add.rn.f32x2 %0, %1, %2;" : "=l"(r) : "l"(a), "l"(b));
    return r;
}
__device__ __forceinline__ c64 pmul(c64 a, c64 b) {
    c64 r;
    asm("mul.rn.f32x2 %0, %1, %2;" : "=l"(r) : "l"(a), "l"(b));
    return r;
}
__device__ __forceinline__ c64 pfma(c64 a, c64 b, c64 c) {
    c64 r;
    asm("fma.rn.f32x2 %0, %1, %2, %3;" : "=l"(r) : "l"(a), "l"(b), "l"(c));
    return r;
}
__device__ __forceinline__ c64 pswap(c64 a) {   // (re,im) -> (im,re)
    c64 r;
    asm("{\n\t.reg .b32 lo, hi;\n\tmov.b64 {lo, hi}, %1;\n\tmov.b64 %0, {hi, lo};\n\t}"
        : "=l"(r) : "l"(a));
    return r;
}

#define K_NEG1 cpack(-1.0f, -1.0f)
#define K_PM   cpack( 1.0f, -1.0f)
#define K_MP   cpack(-1.0f,  1.0f)

// a - b
__device__ __forceinline__ c64 psub(c64 a, c64 b) { return pfma(b, K_NEG1, a); }
// complex mul by twiddle held split: xx=(bx,bx), nyy=(-by,by)
__device__ __forceinline__ c64 cmul_t(c64 a, c64 xx, c64 nyy) {
    return pfma(a, xx, pmul(pswap(a), nyy));
}
// multiply by -i: (x,y) -> (y,-x)
__device__ __forceinline__ c64 cnegi(c64 a) { return pmul(pswap(a), K_PM); }

// forward DFT4 (W4 = -i), packed: 9 f32x2 ops
__device__ __forceinline__ void dft4(c64 a, c64 b, c64 c, c64 d,
                                     c64& o0, c64& o1, c64& o2, c64& o3) {
    c64 s0 = padd(a, c);
    c64 s1 = psub(a, c);
    c64 s2 = padd(b, d);
    c64 s3 = psub(b, d);
    o0 = padd(s0, s2);
    o2 = psub(s0, s2);
    c64 s3r = pswap(s3);
    o1 = pfma(s3r, K_PM, s1);   // (s1x + s3y, s1y - s3x) = s1 - i*s3
    o3 = pfma(s3r, K_MP, s1);   // (s1x - s3y, s1y + s3x) = s1 + i*s3
}

// 16-point forward DFT, natural in -> natural out (radix-4 x radix-4), packed.
__device__ __forceinline__ void fft16(c64 v[16]) {
    const float C1 = 0.92387953251128675613f;  // cos(pi/8)
    const float S1 = 0.38268343236508977173f;  // sin(pi/8)
    const float R  = 0.70710678118654752440f;  // sqrt(2)/2

    c64 a[4][4];
#pragma unroll
    for (int l = 0; l < 4; l++)
        dft4(v[l], v[l + 4], v[l + 8], v[l + 12],
             a[l][0], a[l][1], a[l][2], a[l][3]);

    // internal twiddles W16^{l*p} in split (xx, nyy) form
    a[1][1] = cmul_t(a[1][1], cpack( C1,  C1), cpack( S1, -S1));  // (C1,-S1)
    a[1][2] = cmul_t(a[1][2], cpack(  R,   R), cpack(  R,  -R));  // (R,-R)
    a[1][3] = cmul_t(a[1][3], cpack( S1,  S1), cpack( C1, -C1));  // (S1,-C1)
    a[2][1] = cmul_t(a[2][1], cpack(  R,   R), cpack(  R,  -R));  // (R,-R)
    a[2][2] = cnegi(a[2][2]);                                     // * -i
    a[2][3] = cmul_t(a[2][3], cpack( -R,  -R), cpack(  R,  -R));  // (-R,-R)
    a[3][1] = cmul_t(a[3][1], cpack( S1,  S1), cpack( C1, -C1));  // (S1,-C1)
    a[3][2] = cmul_t(a[3][2], cpack( -R,  -R), cpack(  R,  -R));  // (-R,-R)
    a[3][3] = cmul_t(a[3][3], cpack(-C1, -C1), cpack(-S1,  S1));  // (-C1,S1)

#pragma unroll
    for (int p = 0; p < 4; p++)
        dft4(a[0][p], a[1][p], a[2][p], a[3][p],
             v[p], v[4 + p], v[8 + p], v[12 + p]);
}

// v[k] *= w^k, k=1..15. Base angle ang; split-form recurrence, 7 packed ops/step.
__device__ __forceinline__ void twiddle16(c64 v[16], float ang) {
    float s, c;
    sincosf(ang, &s, &c);
    const c64 cwxx = cpack( c,  c);   // base cos pair
    const c64 wsnn = cpack(-s,  s);   // (-sw, sw)
    const c64 wsnp = cpack( s, -s);   // (sw, -sw)
    c64 ckxx = cwxx;                  // running cos(k*ang) pair
    c64 sknn = wsnn;                  // running (-sin, sin)
#pragma unroll
    for (int k = 1; k < 16; k++) {
        v[k] = cmul_t(v[k], ckxx, sknn);
        // advance: c' = c*cw - s*sw (both lanes), s'nn = (-(s*cw + c*sw), +)
        c64 nc = pfma(ckxx, cwxx, pmul(sknn, wsnp));
        c64 ns = pfma(sknn, cwxx, pmul(ckxx, wsnn));
        ckxx = nc;
        sknn = ns;
    }
}

__global__ void __launch_bounds__(TPB, 4)
fft4096_kernel(const float* __restrict__ xre,
               const float* __restrict__ xim,
               float* __restrict__ out,
               int batch) {
    __shared__ c64 sh[16 * 257];  // 32896 B (257-stride pad for exch 1)

    const int b = blockIdx.x;
    const int t = threadIdx.x;

    const float* xr = xre + (size_t)b * NFFT;
    const float* xi = xim + (size_t)b * NFFT;

    c64 v[16];
#pragma unroll
    for (int n1 = 0; n1 < 16; n1++)
        v[n1] = cpack(__ldcs(&xr[n1 * 256 + t]), __ldcs(&xi[n1 * 256 + t]));

    // ---- pass 1: DFT16 over n1 (thread t = n2), twiddle W4096^{t*k1} ----
    fft16(v);
    twiddle16(v, -6.2831853071795864769f * (float)t / 4096.0f);

    // ---- exchange 1: sh[k1*257 + n2] ----
#pragma unroll
    for (int k1 = 0; k1 < 16; k1++)
        sh[k1 * 257 + t] = v[k1];
    __syncthreads();

    {
        const int k1 = t & 15;
        const int p2 = t >> 4;
#pragma unroll
        for (int p1 = 0; p1 < 16; p1++)
            v[p1] = sh[k1 * 257 + p1 * 16 + p2];

        // ---- pass 2: DFT16 over p1 -> q1, twiddle W256^{p2*q1} ----
        fft16(v);
        twiddle16(v, -6.2831853071795864769f * (float)p2 / 256.0f);
    }
    __syncthreads();

    // ---- exchange 2: sh[q1*256 + t] ----
#pragma unroll
    for (int q1 = 0; q1 < 16; q1++)
        sh[q1 * 256 + t] = v[q1];
    __syncthreads();

    {
        const int k1 = t & 15;
        const int q1 = t >> 4;
#pragma unroll
        for (int p2 = 0; p2 < 16; p2++)
            v[p2] = sh[q1 * 256 + p2 * 16 + k1];
    }

    // ---- pass 3: DFT16 over p2 -> q2;  Y[q2*256 + t] ----
    fft16(v);

    float* outre = out + (size_t)b * NFFT;
    float* outim = out + (size_t)batch * NFFT + (size_t)b * NFFT;
#pragma unroll
    for (int q2 = 0; q2 < 16; q2++) {
        float re, im;
        cunpack(v[q2], re, im);
        __stcs(&outre[q2 * 256 + t], re);
        __stcs(&outim[q2 * 256 + t], im);
    }
}

extern "C" void kernel_launch(void* const* d_in, const int* in_sizes, int n_in,
                              void* d_out, int out_size) {
    const float* xre = (const float*)d_in[0];
    const float* xim = (const float*)d_in[1];
    float* out = (float*)d_out;
    const int batch = in_sizes[0] / NFFT;

    fft4096_kernel<<<batch, TPB>>>(xre, xim, out, batch);
}